// round 9
// baseline (speedup 1.0000x reference)
#include <cuda_runtime.h>
#include <cuda_bf16.h>
#include <float.h>
#include <math.h>

#define HH 8
#define CC 128
#define MAXN 65536
#define GB_NODES 64
#define GB_THREADS 128
#define LOG2E 1.4426950408889634f

// Scratch (allocation-free), aligned so per-node 32B rows support v8 loads.
__device__ __align__(256) float        g_p[MAXN * HH];
__device__ __align__(256) float        g_q[MAXN * HH];
__device__ __align__(256) unsigned int g_m[MAXN * 4];
__device__ __align__(256) float        g_s[MAXN * HH];   // sum -> z = m + log2(s+eps)

// ---------------------------------------------------------------------------
// 256-bit scattered load via texture path (read-only data)
// ---------------------------------------------------------------------------
__device__ __forceinline__ void ldg256nc(const float* __restrict__ addr, float* v) {
    asm volatile("ld.global.nc.v8.f32 {%0,%1,%2,%3,%4,%5,%6,%7}, [%8];"
                 : "=f"(v[0]), "=f"(v[1]), "=f"(v[2]), "=f"(v[3]),
                   "=f"(v[4]), "=f"(v[5]), "=f"(v[6]), "=f"(v[7])
                 : "l"(addr));
}

// ---------------------------------------------------------------------------
// vectorized reductions (sm_90+)
// ---------------------------------------------------------------------------
__device__ __forceinline__ void redMaxBf16v8(unsigned int* addr, const unsigned short* h) {
    asm volatile("red.global.max.noftz.v8.bf16 [%0], {%1,%2,%3,%4,%5,%6,%7,%8};"
                 :: "l"(addr), "h"(h[0]), "h"(h[1]), "h"(h[2]), "h"(h[3]),
                    "h"(h[4]), "h"(h[5]), "h"(h[6]), "h"(h[7]) : "memory");
}
__device__ __forceinline__ void redAddV4(float* addr, float a, float b, float c, float d) {
    asm volatile("red.global.add.v4.f32 [%0], {%1, %2, %3, %4};"
                 :: "l"(addr), "f"(a), "f"(b), "f"(c), "f"(d) : "memory");
}

// bf16 (packed in u32) -> float: widen exactly by moving to high 16 bits
__device__ __forceinline__ float bfLo(unsigned int u) { return __uint_as_float(u << 16); }
__device__ __forceinline__ float bfHi(unsigned int u) { return __uint_as_float(u & 0xFFFF0000u); }

// ---------------------------------------------------------------------------
// K1: block-tile GEMM. 64 nodes/block, x tile transposed in shared.
// Thread (ng, kq) owns 4 nodes x 2 heads; no cross-thread reduction.
// Also initializes m (bf16 -inf) and s (0).
// ---------------------------------------------------------------------------
__global__ __launch_bounds__(GB_THREADS)
void k_gemm(const float* __restrict__ x, const float* __restrict__ W,
            float* __restrict__ p, float* __restrict__ q,
            unsigned int* __restrict__ m, float* __restrict__ s, int N) {
    __shared__ float  ws[16][CC];
    __shared__ float4 xs4[CC][17];
    float* xsf = (float*)xs4;

    int tid   = threadIdx.x;
    int nbase = blockIdx.x * GB_NODES;

    for (int i = tid; i < 256 * HH; i += GB_THREADS) {
        int c = i >> 3, h = i & 7;
        if (c < CC) ws[h][c] = W[i];
        else        ws[HH + h][c - CC] = W[i];
    }

    {
        int c4l = tid >> 2;
        int ro  = tid & 3;
        for (int rb = 0; rb < GB_NODES; rb += 4) {
            int row = rb + ro;
            int n = nbase + row;
            if (n < N) {
                float4 v = *(const float4*)(x + (size_t)n * CC + c4l * 4);
                int cb = c4l * 4;
                xsf[(cb + 0) * 68 + row] = v.x;
                xsf[(cb + 1) * 68 + row] = v.y;
                xsf[(cb + 2) * 68 + row] = v.z;
                xsf[(cb + 3) * 68 + row] = v.w;
            }
        }
    }

    for (int i = tid; i < GB_NODES * HH; i += GB_THREADS) {
        int n = nbase + (i >> 3);
        if (n < N) s[n * HH + (i & 7)] = 0.0f;
    }
    if (tid < GB_NODES && nbase + tid < N)
        *(uint4*)(m + (nbase + tid) * 4) =
            make_uint4(0xFF80FF80u, 0xFF80FF80u, 0xFF80FF80u, 0xFF80FF80u);
    __syncthreads();

    int ng = tid & 15;
    int kq = tid >> 4;
    int k0 = kq * 2;

    float a00 = 0, a01 = 0, a10 = 0, a11 = 0;
    float a20 = 0, a21 = 0, a30 = 0, a31 = 0;
#pragma unroll 4
    for (int c = 0; c < CC; c++) {
        float  w0 = ws[k0][c], w1 = ws[k0 + 1][c];
        float4 xv = xs4[c][ng];
        a00 += xv.x * w0; a01 += xv.x * w1;
        a10 += xv.y * w0; a11 += xv.y * w1;
        a20 += xv.z * w0; a21 += xv.z * w1;
        a30 += xv.w * w0; a31 += xv.w * w1;
    }
    float av0[4] = { a00, a10, a20, a30 };
    float av1[4] = { a01, a11, a21, a31 };
    float* dst = (k0 < HH) ? p : q;
    int h0 = (k0 < HH) ? k0 : k0 - HH;
#pragma unroll
    for (int i = 0; i < 4; i++) {
        int n = nbase + ng * 4 + i;
        if (n < N) {
            dst[n * HH + h0]     = av0[i];
            dst[n * HH + h0 + 1] = av1[i];
        }
    }
}

// ---------------------------------------------------------------------------
// helper: alpha2 (log2-domain) for one edge into av[8] + bf16 halves
// ---------------------------------------------------------------------------
__device__ __forceinline__ void edgeAlpha(const float* __restrict__ p,
                                          const float* __restrict__ q,
                                          const float* __restrict__ b,
                                          int r, int c, float w,
                                          float* av, unsigned short* hb) {
    float pv[HH], qv[HH];
    ldg256nc(p + r * HH, pv);
    ldg256nc(q + c * HH, qv);
#pragma unroll
    for (int h = 0; h < HH; h++) {
        float t = (pv[h] + qv[h] + b[h]) * w;
        t = (t > 0.0f) ? t : 0.2f * t;
        t *= 100.0f * LOG2E;
        av[h] = t;
        __nv_bfloat16 bh = __float2bfloat16_rn(t);
        hb[h] = *(unsigned short*)&bh;
    }
}

// ---------------------------------------------------------------------------
// K2 (pass A): two edges per thread. a2 staged to out, v8.bf16 red.max,
//              row/col written as float2 pairs.
// ---------------------------------------------------------------------------
__global__ void k_passA(const int* __restrict__ row, const int* __restrict__ col,
                        const float* __restrict__ ea,
                        const float* __restrict__ p, const float* __restrict__ q,
                        const float* __restrict__ b,
                        unsigned int* __restrict__ m, float* __restrict__ out,
                        int E, int M, int writeIdx) {
    int i  = blockIdx.x * blockDim.x + threadIdx.x;
    int e0 = 2 * i;
    if (e0 >= M) return;
    bool two = (e0 + 1 < M);

    int r0, c0, r1 = 0, c1 = 0; float w0, w1 = 1.0f;
    if (e0 + 1 < E && two) {            // fast path: both real edges
        int2   rr = *(const int2*)(row + e0);
        int2   cc = *(const int2*)(col + e0);
        float2 aa = __ldcs((const float2*)(ea + e0));
        r0 = rr.x; r1 = rr.y; c0 = cc.x; c1 = cc.y;
        w0 = fabsf(aa.x); w1 = fabsf(aa.y);
    } else {
        if (e0 < E) { r0 = row[e0]; c0 = col[e0]; w0 = fabsf(__ldcs(ea + e0)); }
        else        { r0 = e0 - E;  c0 = r0;      w0 = 1.0f; }
        if (two) {
            int e1 = e0 + 1;
            if (e1 < E) { r1 = row[e1]; c1 = col[e1]; w1 = fabsf(__ldcs(ea + e1)); }
            else        { r1 = e1 - E;  c1 = r1;      w1 = 1.0f; }
        }
    }

    float av0[HH], av1[HH];
    unsigned short hb0[HH], hb1[HH];
    edgeAlpha(p, q, b, r0, c0, w0, av0, hb0);
    if (two) edgeAlpha(p, q, b, r1, c1, w1, av1, hb1);

    redMaxBf16v8(&m[r0 * 4], hb0);
    if (two) redMaxBf16v8(&m[r1 * 4], hb1);

    *(float4*)(out + (size_t)e0 * HH)     = make_float4(av0[0], av0[1], av0[2], av0[3]);
    *(float4*)(out + (size_t)e0 * HH + 4) = make_float4(av0[4], av0[5], av0[6], av0[7]);
    if (two) {
        *(float4*)(out + (size_t)(e0 + 1) * HH)     = make_float4(av1[0], av1[1], av1[2], av1[3]);
        *(float4*)(out + (size_t)(e0 + 1) * HH + 4) = make_float4(av1[4], av1[5], av1[6], av1[7]);
    }

    if (writeIdx) {
        if (two) {
            __stcs((float2*)(out + (size_t)M * HH + e0),     make_float2((float)r0, (float)r1));
            __stcs((float2*)(out + (size_t)M * HH + M + e0), make_float2((float)c0, (float)c1));
        } else {
            __stcs(out + (size_t)M * HH + e0,     (float)r0);
            __stcs(out + (size_t)M * HH + M + e0, (float)c0);
        }
    }
}

// ---------------------------------------------------------------------------
// K3 (pass B): two edges per thread; gather m, s[r] += exp2(a2 - m). No writeback.
// ---------------------------------------------------------------------------
__global__ void k_passB(const int* __restrict__ row,
                        const unsigned int* __restrict__ m, float* __restrict__ s,
                        const float* __restrict__ out, int E, int M) {
    int i  = blockIdx.x * blockDim.x + threadIdx.x;
    int e0 = 2 * i;
    if (e0 >= M) return;
    bool two = (e0 + 1 < M);

    int r0, r1 = 0;
    if (e0 + 1 < E && two) { int2 rr = *(const int2*)(row + e0); r0 = rr.x; r1 = rr.y; }
    else {
        r0 = (e0 < E) ? row[e0] : (e0 - E);
        if (two) { int e1 = e0 + 1; r1 = (e1 < E) ? row[e1] : (e1 - E); }
    }

    float4 a0 = *(const float4*)(out + (size_t)e0 * HH);
    float4 a1 = *(const float4*)(out + (size_t)e0 * HH + 4);
    uint4  mu0 = *(const uint4*)(m + r0 * 4);
    float4 a2 = make_float4(0, 0, 0, 0), a3 = make_float4(0, 0, 0, 0);
    uint4  mu1 = make_uint4(0, 0, 0, 0);
    if (two) {
        a2  = *(const float4*)(out + (size_t)(e0 + 1) * HH);
        a3  = *(const float4*)(out + (size_t)(e0 + 1) * HH + 4);
        mu1 = *(const uint4*)(m + r1 * 4);
    }

    float ev0[HH] = {
        exp2f(a0.x - bfLo(mu0.x)), exp2f(a0.y - bfHi(mu0.x)),
        exp2f(a0.z - bfLo(mu0.y)), exp2f(a0.w - bfHi(mu0.y)),
        exp2f(a1.x - bfLo(mu0.z)), exp2f(a1.y - bfHi(mu0.z)),
        exp2f(a1.z - bfLo(mu0.w)), exp2f(a1.w - bfHi(mu0.w)) };
    redAddV4(&s[r0 * HH],     ev0[0], ev0[1], ev0[2], ev0[3]);
    redAddV4(&s[r0 * HH + 4], ev0[4], ev0[5], ev0[6], ev0[7]);

    if (two) {
        float ev1[HH] = {
            exp2f(a2.x - bfLo(mu1.x)), exp2f(a2.y - bfHi(mu1.x)),
            exp2f(a2.z - bfLo(mu1.y)), exp2f(a2.w - bfHi(mu1.y)),
            exp2f(a3.x - bfLo(mu1.z)), exp2f(a3.y - bfHi(mu1.z)),
            exp2f(a3.z - bfLo(mu1.w)), exp2f(a3.w - bfHi(mu1.w)) };
        redAddV4(&s[r1 * HH],     ev1[0], ev1[1], ev1[2], ev1[3]);
        redAddV4(&s[r1 * HH + 4], ev1[4], ev1[5], ev1[6], ev1[7]);
    }
}

// ---------------------------------------------------------------------------
// K3.5: z = m + log2(s + 1e-16) per (node, head), f32, in place over s
// ---------------------------------------------------------------------------
__global__ void k_z(const unsigned int* __restrict__ m, float* __restrict__ s, int N) {
    int n = blockIdx.x * blockDim.x + threadIdx.x;
    if (n >= N) return;
    uint4 mu = *(const uint4*)(m + n * 4);
    float mv[HH] = { bfLo(mu.x), bfHi(mu.x), bfLo(mu.y), bfHi(mu.y),
                     bfLo(mu.z), bfHi(mu.z), bfLo(mu.w), bfHi(mu.w) };
    float4 s0 = *(const float4*)(s + n * HH);
    float4 s1 = *(const float4*)(s + n * HH + 4);
    float sv[HH] = { s0.x, s0.y, s0.z, s0.w, s1.x, s1.y, s1.z, s1.w };
    float zv[HH];
#pragma unroll
    for (int h = 0; h < HH; h++) zv[h] = mv[h] + __log2f(sv[h] + 1e-16f);
    *(float4*)(s + n * HH)     = make_float4(zv[0], zv[1], zv[2], zv[3]);
    *(float4*)(s + n * HH + 4) = make_float4(zv[4], zv[5], zv[6], zv[7]);
}

// ---------------------------------------------------------------------------
// K4 (pass C): two edges per thread; out = exp2(a2 - z[r]), evict-first store
// ---------------------------------------------------------------------------
__global__ void k_passC(const int* __restrict__ row,
                        const float* __restrict__ s,
                        float* __restrict__ out, int E, int M) {
    int i  = blockIdx.x * blockDim.x + threadIdx.x;
    int e0 = 2 * i;
    if (e0 >= M) return;
    bool two = (e0 + 1 < M);

    int r0, r1 = 0;
    if (e0 + 1 < E && two) { int2 rr = *(const int2*)(row + e0); r0 = rr.x; r1 = rr.y; }
    else {
        r0 = (e0 < E) ? row[e0] : (e0 - E);
        if (two) { int e1 = e0 + 1; r1 = (e1 < E) ? row[e1] : (e1 - E); }
    }

    float4 a0 = __ldlu((const float4*)(out + (size_t)e0 * HH));
    float4 a1 = __ldlu((const float4*)(out + (size_t)e0 * HH + 4));
    float zv0[HH];
    ldg256nc(s + r0 * HH, zv0);

    float4 o0 = make_float4(exp2f(a0.x - zv0[0]), exp2f(a0.y - zv0[1]),
                            exp2f(a0.z - zv0[2]), exp2f(a0.w - zv0[3]));
    float4 o1 = make_float4(exp2f(a1.x - zv0[4]), exp2f(a1.y - zv0[5]),
                            exp2f(a1.z - zv0[6]), exp2f(a1.w - zv0[7]));
    __stcs((float4*)(out + (size_t)e0 * HH),     o0);
    __stcs((float4*)(out + (size_t)e0 * HH + 4), o1);

    if (two) {
        float4 a2 = __ldlu((const float4*)(out + (size_t)(e0 + 1) * HH));
        float4 a3 = __ldlu((const float4*)(out + (size_t)(e0 + 1) * HH + 4));
        float zv1[HH];
        ldg256nc(s + r1 * HH, zv1);
        float4 o2 = make_float4(exp2f(a2.x - zv1[0]), exp2f(a2.y - zv1[1]),
                                exp2f(a2.z - zv1[2]), exp2f(a2.w - zv1[3]));
        float4 o3 = make_float4(exp2f(a3.x - zv1[4]), exp2f(a3.y - zv1[5]),
                                exp2f(a3.z - zv1[6]), exp2f(a3.w - zv1[7]));
        __stcs((float4*)(out + (size_t)(e0 + 1) * HH),     o2);
        __stcs((float4*)(out + (size_t)(e0 + 1) * HH + 4), o3);
    }
}

// ---------------------------------------------------------------------------
extern "C" void kernel_launch(void* const* d_in, const int* in_sizes, int n_in,
                              void* d_out, int out_size) {
    const float* x  = (const float*)d_in[0];   // [N, 128]
    const int*   ei = (const int*)d_in[1];     // [2, E]
    const float* ea = (const float*)d_in[2];   // [E]
    const float* W  = (const float*)d_in[3];   // [256, 8]
    const float* b  = (const float*)d_in[4];   // [8]
    float* out = (float*)d_out;

    int N = in_sizes[0] / CC;
    int E = in_sizes[2];
    int M = E + N;
    const int* row = ei;
    const int* col = ei + E;

    float *p, *q, *s; unsigned int* m;
    cudaGetSymbolAddress((void**)&p, g_p);
    cudaGetSymbolAddress((void**)&q, g_q);
    cudaGetSymbolAddress((void**)&m, g_m);
    cudaGetSymbolAddress((void**)&s, g_s);

    int writeIdx = (out_size >= M * (HH + 2)) ? 1 : 0;

    int gblocks = (N + GB_NODES - 1) / GB_NODES;
    k_gemm<<<gblocks, GB_THREADS>>>(x, W, p, q, m, s, N);

    int pairs   = (M + 1) / 2;
    int eblocks = (pairs + 255) / 256;
    k_passA<<<eblocks, 256>>>(row, col, ea, p, q, b, m, out, E, M, writeIdx);
    k_passB<<<eblocks, 256>>>(row, m, s, out, E, M);
    k_z<<<(N + 255) / 256, 256>>>(m, s, N);
    k_passC<<<eblocks, 256>>>(row, s, out, E, M);
}

// round 10
// speedup vs baseline: 1.0687x; 1.0687x over previous
#include <cuda_runtime.h>
#include <cuda_bf16.h>
#include <float.h>
#include <math.h>

#define HH 8
#define CC 128
#define MAXN 65536
#define GB_NODES 64
#define GB_THREADS 128
#define LOG2E 1.4426950408889634f

// Scratch (allocation-free), aligned so per-node 32B rows support v8 loads.
__device__ __align__(256) float        g_p[MAXN * HH];
__device__ __align__(256) float        g_q[MAXN * HH];
__device__ __align__(256) unsigned int g_m[MAXN * 4];
__device__ __align__(256) float        g_s[MAXN * HH];   // sum -> z = m + log2(s+eps)

// ---------------------------------------------------------------------------
// 256-bit scattered load via texture path (read-only data)
// ---------------------------------------------------------------------------
__device__ __forceinline__ void ldg256nc(const float* __restrict__ addr, float* v) {
    asm volatile("ld.global.nc.v8.f32 {%0,%1,%2,%3,%4,%5,%6,%7}, [%8];"
                 : "=f"(v[0]), "=f"(v[1]), "=f"(v[2]), "=f"(v[3]),
                   "=f"(v[4]), "=f"(v[5]), "=f"(v[6]), "=f"(v[7])
                 : "l"(addr));
}

// ---------------------------------------------------------------------------
// vectorized reductions (sm_90+)
// ---------------------------------------------------------------------------
__device__ __forceinline__ void redMaxBf16v8(unsigned int* addr, const unsigned short* h) {
    asm volatile("red.global.max.noftz.v8.bf16 [%0], {%1,%2,%3,%4,%5,%6,%7,%8};"
                 :: "l"(addr), "h"(h[0]), "h"(h[1]), "h"(h[2]), "h"(h[3]),
                    "h"(h[4]), "h"(h[5]), "h"(h[6]), "h"(h[7]) : "memory");
}
__device__ __forceinline__ void redAddV4(float* addr, float a, float b, float c, float d) {
    asm volatile("red.global.add.v4.f32 [%0], {%1, %2, %3, %4};"
                 :: "l"(addr), "f"(a), "f"(b), "f"(c), "f"(d) : "memory");
}

// bf16 (packed in u32) -> float: widen exactly by moving to high 16 bits
__device__ __forceinline__ float bfLo(unsigned int u) { return __uint_as_float(u << 16); }
__device__ __forceinline__ float bfHi(unsigned int u) { return __uint_as_float(u & 0xFFFF0000u); }

// ---------------------------------------------------------------------------
// K1: block-tile GEMM. 64 nodes/block, x tile transposed in shared.
// Thread (ng, kq) owns 4 nodes x 2 heads; no cross-thread reduction.
// Also initializes m (bf16 -inf) and s (0).
// ---------------------------------------------------------------------------
__global__ __launch_bounds__(GB_THREADS)
void k_gemm(const float* __restrict__ x, const float* __restrict__ W,
            float* __restrict__ p, float* __restrict__ q,
            unsigned int* __restrict__ m, float* __restrict__ s, int N) {
    __shared__ float  ws[16][CC];
    __shared__ float4 xs4[CC][17];
    float* xsf = (float*)xs4;

    int tid   = threadIdx.x;
    int nbase = blockIdx.x * GB_NODES;

    for (int i = tid; i < 256 * HH; i += GB_THREADS) {
        int c = i >> 3, h = i & 7;
        if (c < CC) ws[h][c] = W[i];
        else        ws[HH + h][c - CC] = W[i];
    }

    {
        int c4l = tid >> 2;
        int ro  = tid & 3;
        for (int rb = 0; rb < GB_NODES; rb += 4) {
            int row = rb + ro;
            int n = nbase + row;
            if (n < N) {
                float4 v = *(const float4*)(x + (size_t)n * CC + c4l * 4);
                int cb = c4l * 4;
                xsf[(cb + 0) * 68 + row] = v.x;
                xsf[(cb + 1) * 68 + row] = v.y;
                xsf[(cb + 2) * 68 + row] = v.z;
                xsf[(cb + 3) * 68 + row] = v.w;
            }
        }
    }

    for (int i = tid; i < GB_NODES * HH; i += GB_THREADS) {
        int n = nbase + (i >> 3);
        if (n < N) s[n * HH + (i & 7)] = 0.0f;
    }
    if (tid < GB_NODES && nbase + tid < N)
        *(uint4*)(m + (nbase + tid) * 4) =
            make_uint4(0xFF80FF80u, 0xFF80FF80u, 0xFF80FF80u, 0xFF80FF80u);
    __syncthreads();

    int ng = tid & 15;
    int kq = tid >> 4;
    int k0 = kq * 2;

    float a00 = 0, a01 = 0, a10 = 0, a11 = 0;
    float a20 = 0, a21 = 0, a30 = 0, a31 = 0;
#pragma unroll 4
    for (int c = 0; c < CC; c++) {
        float  w0 = ws[k0][c], w1 = ws[k0 + 1][c];
        float4 xv = xs4[c][ng];
        a00 += xv.x * w0; a01 += xv.x * w1;
        a10 += xv.y * w0; a11 += xv.y * w1;
        a20 += xv.z * w0; a21 += xv.z * w1;
        a30 += xv.w * w0; a31 += xv.w * w1;
    }
    float av0[4] = { a00, a10, a20, a30 };
    float av1[4] = { a01, a11, a21, a31 };
    float* dst = (k0 < HH) ? p : q;
    int h0 = (k0 < HH) ? k0 : k0 - HH;
#pragma unroll
    for (int i = 0; i < 4; i++) {
        int n = nbase + ng * 4 + i;
        if (n < N) {
            dst[n * HH + h0]     = av0[i];
            dst[n * HH + h0 + 1] = av1[i];
        }
    }
}

// ---------------------------------------------------------------------------
// K2 (pass A): a2 = leaky((p[r]+q[c]+b)*|ea|)*100*log2e -> out (staged)
//              one v8.bf16 red.max per edge (row/col writes moved to pass C)
// ---------------------------------------------------------------------------
__global__ void k_passA(const int* __restrict__ row, const int* __restrict__ col,
                        const float* __restrict__ ea,
                        const float* __restrict__ p, const float* __restrict__ q,
                        const float* __restrict__ b,
                        unsigned int* __restrict__ m, float* __restrict__ out,
                        int E, int M) {
    int e = blockIdx.x * blockDim.x + threadIdx.x;
    if (e >= M) return;
    int r, c; float w;
    if (e < E) { r = row[e]; c = col[e]; w = fabsf(__ldcs(ea + e)); }
    else       { r = e - E;  c = r;      w = 1.0f; }

    float pv[HH], qv[HH];
    ldg256nc(p + r * HH, pv);
    ldg256nc(q + c * HH, qv);

    float av[HH];
    unsigned short hb[HH];
#pragma unroll
    for (int h = 0; h < HH; h++) {
        float t = (pv[h] + qv[h] + b[h]) * w;
        t = (t > 0.0f) ? t : 0.2f * t;
        t *= 100.0f * LOG2E;            // stage in log2 domain, exp2-ready
        av[h] = t;
        __nv_bfloat16 bh = __float2bfloat16_rn(t);
        hb[h] = *(unsigned short*)&bh;
    }
    redMaxBf16v8(&m[r * 4], hb);

    *(float4*)(out + (size_t)e * HH)     = make_float4(av[0], av[1], av[2], av[3]);
    *(float4*)(out + (size_t)e * HH + 4) = make_float4(av[4], av[5], av[6], av[7]);
}

// ---------------------------------------------------------------------------
// K3 (pass B): read staged a2 (coalesced), gather m (1 x 16B scattered),
//              s[r] += exp2(a2 - m). NO writeback.
// ---------------------------------------------------------------------------
__global__ void k_passB(const int* __restrict__ row,
                        const unsigned int* __restrict__ m, float* __restrict__ s,
                        const float* __restrict__ out, int E, int M) {
    int e = blockIdx.x * blockDim.x + threadIdx.x;
    if (e >= M) return;
    int r = (e < E) ? row[e] : (e - E);

    float4 a0 = *(const float4*)(out + (size_t)e * HH);
    float4 a1 = *(const float4*)(out + (size_t)e * HH + 4);
    uint4  mu = *(const uint4*)(m + r * 4);

    float ev[HH] = {
        exp2f(a0.x - bfLo(mu.x)), exp2f(a0.y - bfHi(mu.x)),
        exp2f(a0.z - bfLo(mu.y)), exp2f(a0.w - bfHi(mu.y)),
        exp2f(a1.x - bfLo(mu.z)), exp2f(a1.y - bfHi(mu.z)),
        exp2f(a1.z - bfLo(mu.w)), exp2f(a1.w - bfHi(mu.w)) };

    redAddV4(&s[r * HH],     ev[0], ev[1], ev[2], ev[3]);
    redAddV4(&s[r * HH + 4], ev[4], ev[5], ev[6], ev[7]);
}

// ---------------------------------------------------------------------------
// K3.5: z = m + log2(s + 1e-16), one thread per half-row (2N threads)
// ---------------------------------------------------------------------------
__global__ void k_z(const unsigned int* __restrict__ m, float* __restrict__ s, int N2) {
    int i = blockIdx.x * blockDim.x + threadIdx.x;
    if (i >= N2) return;
    int n = i >> 1, half = i & 1;

    uint2  mu = *(const uint2*)(m + n * 4 + half * 2);
    float4 sv = *(const float4*)(s + n * HH + half * 4);
    float4 zv;
    zv.x = bfLo(mu.x) + __log2f(sv.x + 1e-16f);
    zv.y = bfHi(mu.x) + __log2f(sv.y + 1e-16f);
    zv.z = bfLo(mu.y) + __log2f(sv.z + 1e-16f);
    zv.w = bfHi(mu.y) + __log2f(sv.w + 1e-16f);
    *(float4*)(s + n * HH + half * 4) = zv;
}

// ---------------------------------------------------------------------------
// K4 (pass C): read staged a2 (last-use), gather z (1 x 256-bit),
//              out = exp2(a2 - z); also write row/col outputs (evict-first)
// ---------------------------------------------------------------------------
__global__ void k_passC(const int* __restrict__ row, const int* __restrict__ col,
                        const float* __restrict__ s,
                        float* __restrict__ out, int E, int M, int writeIdx) {
    int e = blockIdx.x * blockDim.x + threadIdx.x;
    if (e >= M) return;
    int r, c;
    if (e < E) { r = row[e]; c = col[e]; }
    else       { r = e - E;  c = r; }

    float4 a0 = __ldlu((const float4*)(out + (size_t)e * HH));
    float4 a1 = __ldlu((const float4*)(out + (size_t)e * HH + 4));
    float zv[HH];
    ldg256nc(s + r * HH, zv);

    float4 o0 = make_float4(exp2f(a0.x - zv[0]), exp2f(a0.y - zv[1]),
                            exp2f(a0.z - zv[2]), exp2f(a0.w - zv[3]));
    float4 o1 = make_float4(exp2f(a1.x - zv[4]), exp2f(a1.y - zv[5]),
                            exp2f(a1.z - zv[6]), exp2f(a1.w - zv[7]));
    __stcs((float4*)(out + (size_t)e * HH),     o0);
    __stcs((float4*)(out + (size_t)e * HH + 4), o1);

    if (writeIdx) {
        __stcs(out + (size_t)M * HH + e,     (float)r);
        __stcs(out + (size_t)M * HH + M + e, (float)c);
    }
}

// ---------------------------------------------------------------------------
extern "C" void kernel_launch(void* const* d_in, const int* in_sizes, int n_in,
                              void* d_out, int out_size) {
    const float* x  = (const float*)d_in[0];   // [N, 128]
    const int*   ei = (const int*)d_in[1];     // [2, E]
    const float* ea = (const float*)d_in[2];   // [E]
    const float* W  = (const float*)d_in[3];   // [256, 8]
    const float* b  = (const float*)d_in[4];   // [8]
    float* out = (float*)d_out;

    int N = in_sizes[0] / CC;
    int E = in_sizes[2];
    int M = E + N;
    const int* row = ei;
    const int* col = ei + E;

    float *p, *q, *s; unsigned int* m;
    cudaGetSymbolAddress((void**)&p, g_p);
    cudaGetSymbolAddress((void**)&q, g_q);
    cudaGetSymbolAddress((void**)&m, g_m);
    cudaGetSymbolAddress((void**)&s, g_s);

    int writeIdx = (out_size >= M * (HH + 2)) ? 1 : 0;

    int gblocks = (N + GB_NODES - 1) / GB_NODES;
    k_gemm<<<gblocks, GB_THREADS>>>(x, W, p, q, m, s, N);

    int eblocks = (M + 255) / 256;
    k_passA<<<eblocks, 256>>>(row, col, ea, p, q, b, m, out, E, M);
    k_passB<<<eblocks, 256>>>(row, m, s, out, E, M);
    k_z<<<(2 * N + 255) / 256, 256>>>(m, s, 2 * N);
    k_passC<<<eblocks, 256>>>(row, col, s, out, E, M, writeIdx);
}